// round 1
// baseline (speedup 1.0000x reference)
#include <cuda_runtime.h>

// LSTM_21869973471591 — B=4096, T=200, IN=2, H=64 (gates 4H=256)
//
// Design: one CTA (256 threads) owns NB=28 batch rows for the whole T loop.
// Thread j owns gate row j of W_hh (64 weights, register-resident as 32
// packed f32x2 values). Per step, gates[b][j] = xg + sum_k W_hh[j][k]*h[b][k]
// computed with fma.rn.f32x2 (2 k's per op), h broadcast from smem (LDS.128).
// The 28 rows are split into two groups of 14 and software-pipelined so the
// MUFU-heavy activation of one group hides under the FMA-bound gate phase of
// the other. c-state lives in registers; h lives in smem; x is staged through
// smem in 20-step chunks.

#define B_TOT    4096
#define T_LEN    200
#define IN_DIM   2
#define H_DIM    64
#define G_DIM    256
#define NB       28
#define NBH      14
#define CH       20          // x chunk length in timesteps (200 % 20 == 0)
#define NTHREADS 256
#define NBLOCKS  ((B_TOT + NB - 1) / NB)   // 147

__device__ __forceinline__ unsigned long long pack2(float lo, float hi) {
    unsigned long long r;
    asm("mov.b64 %0, {%1, %2};" : "=l"(r) : "f"(lo), "f"(hi));
    return r;
}
__device__ __forceinline__ void unpack2(unsigned long long v, float& lo, float& hi) {
    asm("mov.b64 {%0, %1}, %2;" : "=f"(lo), "=f"(hi) : "l"(v));
}
// packed dual FMA: acc = a * b + acc (lane-wise f32x2)
__device__ __forceinline__ void fma2(unsigned long long& acc,
                                     unsigned long long a, unsigned long long b) {
    asm("fma.rn.f32x2 %0, %1, %2, %0;" : "+l"(acc) : "l"(a), "l"(b));
}
__device__ __forceinline__ float fast_rcp(float x) {
    float r; asm("rcp.approx.f32 %0, %1;" : "=f"(r) : "f"(x)); return r;
}
__device__ __forceinline__ float fast_ex2(float x) {
    float r; asm("ex2.approx.f32 %0, %1;" : "=f"(r) : "f"(x)); return r;
}
// accurate-enough sigmoid/tanh built from ex2.approx (~2^-22) + rcp.approx,
// NOT tanh.approx (~2^-10 would risk the 1e-3 bound over 200 recurrent steps)
__device__ __forceinline__ float sigmoid_f(float x) {
    // 1 / (1 + exp(-x)) ; exp(-x) = ex2(-x * log2(e))
    float e = fast_ex2(-1.4426950408889634f * x);
    return fast_rcp(1.0f + e);
}
__device__ __forceinline__ float tanh_f(float x) {
    // 1 - 2 / (exp(2x) + 1)
    float e = fast_ex2(2.8853900817779268f * x);
    return fmaf(-2.0f, fast_rcp(1.0f + e), 1.0f);
}

__global__ __launch_bounds__(NTHREADS)
void lstm_kernel(const float* __restrict__ x,      // [B, T, IN]
                 const float* __restrict__ W_ih,   // [4H, IN]
                 const float* __restrict__ W_hh,   // [4H, H]
                 const float* __restrict__ b_ih,   // [4H]
                 const float* __restrict__ b_hh,   // [4H]
                 const float* __restrict__ W_fc,   // [1, H]
                 const float* __restrict__ b_fc,   // [1]
                 float* __restrict__ out)          // [B, 1]
{
    __shared__ float x_s[NB][CH * IN_DIM];   // 4480 B
    __shared__ float h_s[NB][H_DIM];         // 7168 B
    __shared__ float g_s[NB][G_DIM];         // 28672 B

    const int tid  = threadIdx.x;
    const int j    = tid;                    // gate row owned by this thread
    const int row0 = blockIdx.x * NB;

    // per-gate-row constants
    const float wi0  = W_ih[j * IN_DIM + 0];
    const float wi1  = W_ih[j * IN_DIM + 1];
    const float bias = b_ih[j] + b_hh[j];

    // W_hh row j, register-resident as 32 packed pairs {w[2m], w[2m+1]}
    unsigned long long w2[H_DIM / 2];
    {
        const float4* wrow = reinterpret_cast<const float4*>(W_hh + j * H_DIM);
        #pragma unroll
        for (int k4 = 0; k4 < H_DIM / 4; k4++) {
            float4 v = wrow[k4];
            w2[2 * k4 + 0] = pack2(v.x, v.y);
            w2[2 * k4 + 1] = pack2(v.z, v.w);
        }
    }

    // h0 = 0, c0 = 0
    for (int i = tid; i < NB * H_DIM; i += NTHREADS)
        (&h_s[0][0])[i] = 0.0f;
    float cA[4] = {0.f, 0.f, 0.f, 0.f};
    float cB[4] = {0.f, 0.f, 0.f, 0.f};
    __syncthreads();

    // gate phase for a 14-row group starting at b0, timestep offset tc in chunk
    auto gate_phase = [&](int b0, int tc) {
        unsigned long long acc[NBH];
        #pragma unroll
        for (int b = 0; b < NBH; b++) {
            float2 xv = *reinterpret_cast<const float2*>(&x_s[b0 + b][tc * IN_DIM]);
            float xg  = fmaf(xv.y, wi1, fmaf(xv.x, wi0, bias));
            acc[b]    = pack2(xg, 0.0f);
        }
        #pragma unroll
        for (int k4 = 0; k4 < H_DIM / 4; k4++) {
            #pragma unroll
            for (int b = 0; b < NBH; b++) {
                ulonglong2 hv = *reinterpret_cast<const ulonglong2*>(&h_s[b0 + b][k4 * 4]);
                fma2(acc[b], w2[2 * k4 + 0], hv.x);
                fma2(acc[b], w2[2 * k4 + 1], hv.y);
            }
        }
        #pragma unroll
        for (int b = 0; b < NBH; b++) {
            float lo, hi; unpack2(acc[b], lo, hi);
            g_s[b0 + b][j] = lo + hi;
        }
    };

    // activation phase for a 14-row group; c-state in caller's registers
    auto act_phase = [&](int b0, float* c) {
        #pragma unroll
        for (int ii = 0; ii < 4; ii++) {
            int it = tid + ii * NTHREADS;
            if (it < NBH * H_DIM) {
                int b = b0 + (it >> 6);
                int n = it & 63;
                float gi = g_s[b][n];
                float gf = g_s[b][64 + n];
                float gg = g_s[b][128 + n];
                float go = g_s[b][192 + n];
                float iv = sigmoid_f(gi);
                float fv = sigmoid_f(gf);
                float ov = sigmoid_f(go);
                float gv = tanh_f(gg);
                float cv = fmaf(fv, c[ii], iv * gv);
                c[ii] = cv;
                h_s[b][n] = ov * tanh_f(cv);
            }
        }
    };

    for (int t = 0; t < T_LEN; t++) {
        const int tc = t % CH;
        if (tc == 0) {
            // stage x[t .. t+CH) for all 28 rows (coalesced, rows clamped for tail block)
            for (int idx = tid; idx < NB * CH * IN_DIM; idx += NTHREADS) {
                int b = idx / (CH * IN_DIM);
                int r = idx - b * (CH * IN_DIM);
                int row = row0 + b; if (row > B_TOT - 1) row = B_TOT - 1;
                x_s[b][r] = x[row * (T_LEN * IN_DIM) + t * IN_DIM + r];
            }
            __syncthreads();
        }
        // phase 1: gates(groupA, t) overlapped with act(groupB, t-1)
        gate_phase(0, tc);
        if (t > 0) act_phase(NBH, cB);
        __syncthreads();
        // phase 2: gates(groupB, t) overlapped with act(groupA, t)
        gate_phase(NBH, tc);
        act_phase(0, cA);
        __syncthreads();
    }
    // drain: act(groupB, T-1)
    act_phase(NBH, cB);
    __syncthreads();

    // fc head: out[b] = h_last[b] . W_fc + b_fc
    if (tid < NB) {
        int row = row0 + tid;
        if (row < B_TOT) {
            float s = b_fc[0];
            #pragma unroll
            for (int n = 0; n < H_DIM; n++)
                s = fmaf(h_s[tid][n], W_fc[n], s);
            out[row] = s;
        }
    }
}

extern "C" void kernel_launch(void* const* d_in, const int* in_sizes, int n_in,
                              void* d_out, int out_size) {
    const float* x    = (const float*)d_in[0];
    const float* W_ih = (const float*)d_in[1];
    const float* W_hh = (const float*)d_in[2];
    const float* b_ih = (const float*)d_in[3];
    const float* b_hh = (const float*)d_in[4];
    const float* W_fc = (const float*)d_in[5];
    const float* b_fc = (const float*)d_in[6];
    float* out = (float*)d_out;
    (void)in_sizes; (void)n_in; (void)out_size;

    lstm_kernel<<<NBLOCKS, NTHREADS>>>(x, W_ih, W_hh, b_ih, b_hh, W_fc, b_fc, out);
}

// round 2
// speedup vs baseline: 1.5659x; 1.5659x over previous
#include <cuda_runtime.h>

// LSTM_21869973471591 — B=4096, T=200, IN=2, H=64 (gates 4H=256)
//
// R2: same algorithm as R1 (thread j owns gate row j of W_hh in registers as
// packed f32x2; h broadcast from smem; act/gate software pipelining), but
// NB=14 rows per CTA and 293 CTAs -> 2 CTAs per SM (16 warps, 4 per SMSP).
// R1 ncu showed occ=12.5%, issue=28.7%, fma=29.9%: the FMA pipe was starved
// by LDS/MUFU latency with only 2 warps/SMSP. Doubling resident warps (and
// letting two independent CTAs overlap act vs gate phases) targets the
// ~565us FFMA2-rt3 issue floor.

#define B_TOT    4096
#define T_LEN    200
#define IN_DIM   2
#define H_DIM    64
#define G_DIM    256
#define NB       14
#define NBH      7
#define CH       20          // x chunk length in timesteps (200 % 20 == 0)
#define NTHREADS 256
#define NBLOCKS  ((B_TOT + NB - 1) / NB)   // 293

__device__ __forceinline__ unsigned long long pack2(float lo, float hi) {
    unsigned long long r;
    asm("mov.b64 %0, {%1, %2};" : "=l"(r) : "f"(lo), "f"(hi));
    return r;
}
__device__ __forceinline__ void unpack2(unsigned long long v, float& lo, float& hi) {
    asm("mov.b64 {%0, %1}, %2;" : "=f"(lo), "=f"(hi) : "l"(v));
}
// packed dual FMA: acc = a * b + acc (lane-wise f32x2)
__device__ __forceinline__ void fma2(unsigned long long& acc,
                                     unsigned long long a, unsigned long long b) {
    asm("fma.rn.f32x2 %0, %1, %2, %0;" : "+l"(acc) : "l"(a), "l"(b));
}
__device__ __forceinline__ float fast_rcp(float x) {
    float r; asm("rcp.approx.f32 %0, %1;" : "=f"(r) : "f"(x)); return r;
}
__device__ __forceinline__ float fast_ex2(float x) {
    float r; asm("ex2.approx.f32 %0, %1;" : "=f"(r) : "f"(x)); return r;
}
// accurate sigmoid/tanh from ex2.approx (~2^-22) + rcp.approx; NOT
// tanh.approx (2^-10 would erode the 1e-3 budget over 200 recurrent steps)
__device__ __forceinline__ float sigmoid_f(float x) {
    float e = fast_ex2(-1.4426950408889634f * x);
    return fast_rcp(1.0f + e);
}
__device__ __forceinline__ float tanh_f(float x) {
    float e = fast_ex2(2.8853900817779268f * x);
    return fmaf(-2.0f, fast_rcp(1.0f + e), 1.0f);
}

__global__ __launch_bounds__(NTHREADS, 2)
void lstm_kernel(const float* __restrict__ x,      // [B, T, IN]
                 const float* __restrict__ W_ih,   // [4H, IN]
                 const float* __restrict__ W_hh,   // [4H, H]
                 const float* __restrict__ b_ih,   // [4H]
                 const float* __restrict__ b_hh,   // [4H]
                 const float* __restrict__ W_fc,   // [1, H]
                 const float* __restrict__ b_fc,   // [1]
                 float* __restrict__ out)          // [B, 1]
{
    __shared__ float x_s[NB][CH * IN_DIM];   // 2240 B
    __shared__ float h_s[NB][H_DIM];         // 3584 B
    __shared__ float g_s[NB][G_DIM];         // 14336 B

    const int tid  = threadIdx.x;
    const int j    = tid;                    // gate row owned by this thread
    const int row0 = blockIdx.x * NB;

    // per-gate-row constants
    const float wi0  = W_ih[j * IN_DIM + 0];
    const float wi1  = W_ih[j * IN_DIM + 1];
    const float bias = b_ih[j] + b_hh[j];

    // W_hh row j, register-resident as 32 packed pairs {w[2m], w[2m+1]}
    unsigned long long w2[H_DIM / 2];
    {
        const float4* wrow = reinterpret_cast<const float4*>(W_hh + j * H_DIM);
        #pragma unroll
        for (int k4 = 0; k4 < H_DIM / 4; k4++) {
            float4 v = wrow[k4];
            w2[2 * k4 + 0] = pack2(v.x, v.y);
            w2[2 * k4 + 1] = pack2(v.z, v.w);
        }
    }

    // h0 = 0, c0 = 0
    for (int i = tid; i < NB * H_DIM; i += NTHREADS)
        (&h_s[0][0])[i] = 0.0f;
    float cA[2] = {0.f, 0.f};
    float cB[2] = {0.f, 0.f};
    __syncthreads();

    // gate phase for a 7-row group starting at b0, timestep offset tc in chunk
    auto gate_phase = [&](int b0, int tc) {
        unsigned long long acc[NBH];
        #pragma unroll
        for (int b = 0; b < NBH; b++) {
            float2 xv = *reinterpret_cast<const float2*>(&x_s[b0 + b][tc * IN_DIM]);
            float xg  = fmaf(xv.y, wi1, fmaf(xv.x, wi0, bias));
            acc[b]    = pack2(xg, 0.0f);
        }
        #pragma unroll
        for (int k4 = 0; k4 < H_DIM / 4; k4++) {
            #pragma unroll
            for (int b = 0; b < NBH; b++) {
                ulonglong2 hv = *reinterpret_cast<const ulonglong2*>(&h_s[b0 + b][k4 * 4]);
                fma2(acc[b], w2[2 * k4 + 0], hv.x);
                fma2(acc[b], w2[2 * k4 + 1], hv.y);
            }
        }
        #pragma unroll
        for (int b = 0; b < NBH; b++) {
            float lo, hi; unpack2(acc[b], lo, hi);
            g_s[b0 + b][j] = lo + hi;
        }
    };

    // activation phase for a 7-row group (448 elements); c-state in registers
    auto act_phase = [&](int b0, float* c) {
        #pragma unroll
        for (int ii = 0; ii < 2; ii++) {
            int it = tid + ii * NTHREADS;
            if (it < NBH * H_DIM) {
                int b = b0 + (it >> 6);
                int n = it & 63;
                float gi = g_s[b][n];
                float gf = g_s[b][64 + n];
                float gg = g_s[b][128 + n];
                float go = g_s[b][192 + n];
                float iv = sigmoid_f(gi);
                float fv = sigmoid_f(gf);
                float ov = sigmoid_f(go);
                float gv = tanh_f(gg);
                float cv = fmaf(fv, c[ii], iv * gv);
                c[ii] = cv;
                h_s[b][n] = ov * tanh_f(cv);
            }
        }
    };

    for (int t = 0; t < T_LEN; t++) {
        const int tc = t % CH;
        if (tc == 0) {
            // stage x[t .. t+CH) for all 14 rows (rows clamped for tail block)
            for (int idx = tid; idx < NB * CH * IN_DIM; idx += NTHREADS) {
                int b = idx / (CH * IN_DIM);
                int r = idx - b * (CH * IN_DIM);
                int row = row0 + b; if (row > B_TOT - 1) row = B_TOT - 1;
                x_s[b][r] = x[row * (T_LEN * IN_DIM) + t * IN_DIM + r];
            }
            __syncthreads();
        }
        // phase 1: gates(groupA, t) overlapped with act(groupB, t-1)
        gate_phase(0, tc);
        if (t > 0) act_phase(NBH, cB);
        __syncthreads();
        // phase 2: gates(groupB, t) overlapped with act(groupA, t)
        gate_phase(NBH, tc);
        act_phase(0, cA);
        __syncthreads();
    }
    // drain: act(groupB, T-1)
    act_phase(NBH, cB);
    __syncthreads();

    // fc head: out[b] = h_last[b] . W_fc + b_fc
    if (tid < NB) {
        int row = row0 + tid;
        if (row < B_TOT) {
            float s = b_fc[0];
            #pragma unroll
            for (int n = 0; n < H_DIM; n++)
                s = fmaf(h_s[tid][n], W_fc[n], s);
            out[row] = s;
        }
    }
}

extern "C" void kernel_launch(void* const* d_in, const int* in_sizes, int n_in,
                              void* d_out, int out_size) {
    const float* x    = (const float*)d_in[0];
    const float* W_ih = (const float*)d_in[1];
    const float* W_hh = (const float*)d_in[2];
    const float* b_ih = (const float*)d_in[3];
    const float* b_hh = (const float*)d_in[4];
    const float* W_fc = (const float*)d_in[5];
    const float* b_fc = (const float*)d_in[6];
    float* out = (float*)d_out;
    (void)in_sizes; (void)n_in; (void)out_size;

    lstm_kernel<<<NBLOCKS, NTHREADS>>>(x, W_ih, W_hh, b_ih, b_hh, W_fc, b_fc, out);
}